// round 11
// baseline (speedup 1.0000x reference)
#include <cuda_runtime.h>

#define Bz 4
#define C_IN 32
#define NPIX 4096                        // 64*64 pooled pixels
#define NODES_PER_B (NPIX * C_IN)        // 131072
#define NODES_TOTAL (Bz * NODES_PER_B)   // 524288
#define ADJ_PER_B   ((long)NPIX * NPIX)  // 16777216 floats
#define EPSV 1e-6f

#define POOL_BLOCKS 64
#define TILES_PER_B 1024                 // 64KB tile = 4 adj rows
#define ZERO_BLOCKS (Bz * TILES_PER_B)   // 4096

// 256-bit zero store (sm_100+): 32 bytes per STG, half the wavefronts of STG.128
__device__ __forceinline__ void st_zero32(void* p)
{
    asm volatile("st.global.v8.b32 [%0], {%1,%1,%1,%1,%1,%1,%1,%1};"
                 :: "l"(p), "r"(0) : "memory");
}

// patch certainty for pooled pixel p of batch b (x_var is 1MB, L2-resident)
__device__ __forceinline__ float certainty(const float4* __restrict__ xv4, int b, int p)
{
    int R = p >> 6, C = p & 63;
    float s = 0.f;
    #pragma unroll
    for (int i = 0; i < 4; ++i) {
        float4 v = __ldg(&xv4[((b * 256 + (R * 4 + i)) << 6) + C]);
        s += v.x + v.y + v.z + v.w;
    }
    return 1.f - s * (1.f / 16.f);
}

__global__ __launch_bounds__(256) void fused_all(
    const float* __restrict__ x_feat,
    const float* __restrict__ x_var,
    float* __restrict__ out)
{
    int blk = blockIdx.x;
    int tid = threadIdx.x;

    if (blk < POOL_BLOCKS) {
        // ---- nodes: channel-summed 4x4 pool of x_feat, tiled 32x ----
        int g   = blk * 256 + tid;       // (b, t)
        int b   = g >> 12;
        int t   = g & 4095;
        int R   = t >> 6;
        int Cc  = t & 63;

        const float4* xf4 = (const float4*)x_feat;
        float s = 0.f;
        for (int c = 0; c < C_IN; ++c) {
            #pragma unroll
            for (int i = 0; i < 4; ++i) {
                float4 v = __ldg(&xf4[(((b * C_IN + c) * 256 + (R * 4 + i)) << 6) + Cc]);
                s += v.x + v.y + v.z + v.w;
            }
        }
        s *= (1.f / 16.f);

        float* nodes = out + (long)b * NODES_PER_B;
        #pragma unroll
        for (int j = 0; j < 32; ++j)
            nodes[j * NPIX + t] = s;     // coalesced across t
        return;
    }

    // ---- adjacency tile: one 64KB tile (4 rows) per block ----
    int tile = blk - POOL_BLOCKS;        // 0..4095
    int b    = tile >> 10;               // batch
    int f0   = (tile & 1023) << 2;       // first adj row of this tile

    float* adjb = out + NODES_TOTAL + (long)b * ADJ_PER_B;

    // Phase a: zero 64KB with 256-bit stores; 8 per thread off one base.
    {
        char* base = (char*)(adjb + (long)f0 * NPIX) + tid * 32;
        #pragma unroll
        for (int k = 0; k < 8; ++k)
            st_zero32(base + k * 8192);
    }

    __syncthreads();   // orders the zeros before the patch stores below

    // Phase b: patch at most 16 candidate edges (4 rows x 4 neighbors).
    if (tid < 16) {
        int f   = f0 + (tid >> 2);
        int sel = tid & 3;
        int t; bool valid;
        if      (sel == 0) { t = f - 64; valid = (f >= 64);        }
        else if (sel == 1) { t = f + 64; valid = (f < NPIX - 64);  }
        else if (sel == 2) { t = f - 1;  valid = ((f & 63) != 0);  }
        else               { t = f + 1;  valid = ((f & 63) != 63); }
        if (valid) {
            const float4* xv4 = (const float4*)x_var;
            float w = certainty(xv4, b, f) - certainty(xv4, b, t);
            if (w > EPSV)
                adjb[(long)f * NPIX + t] = w;
        }
    }
}

extern "C" void kernel_launch(void* const* d_in, const int* in_sizes, int n_in,
                              void* d_out, int out_size)
{
    const float* x_feat = (const float*)d_in[0];
    const float* x_var  = (const float*)d_in[1];
    float* out = (float*)d_out;

    fused_all<<<POOL_BLOCKS + ZERO_BLOCKS, 256>>>(x_feat, x_var, out);
}

// round 12
// speedup vs baseline: 1.1099x; 1.1099x over previous
#include <cuda_runtime.h>

#define Bz 4
#define C_IN 32
#define NPIX 4096                        // 64*64 pooled pixels
#define NODES_PER_B (NPIX * C_IN)        // 131072
#define NODES_TOTAL (Bz * NODES_PER_B)   // 524288
#define ADJ_PER_B   ((long)NPIX * NPIX)  // 16777216 floats
#define EPSV 1e-6f

// patch certainty for pooled pixel p of batch b (x_var is 1MB, L2-resident)
__device__ __forceinline__ float certainty(const float4* __restrict__ xv4, int b, int p)
{
    int R = p >> 6, C = p & 63;
    float s = 0.f;
    #pragma unroll
    for (int i = 0; i < 4; ++i) {
        float4 v = __ldg(&xv4[((b * 256 + (R * 4 + i)) << 6) + C]);
        s += v.x + v.y + v.z + v.w;
    }
    return 1.f - s * (1.f / 16.f);
}

// 256 blocks x 512 threads; block = one pooled row (b, R).
// 16 independent coalesced float4 loads per thread, 2 barriers,
// then tiled nodes stores + sparse edge patches (after memset, same stream).
__global__ __launch_bounds__(512) void patch_all(
    const float* __restrict__ x_feat,
    const float* __restrict__ x_var,
    float* __restrict__ out)
{
    __shared__ float red[8][64];         // [channel-group][Cc]
    __shared__ float sums[64];

    int blk = blockIdx.x;                // 0..255
    int b   = blk >> 6;                  // batch
    int R   = blk & 63;                  // pooled row

    int tid = threadIdx.x;               // 0..511
    int cg  = tid >> 6;                  // channel group (4 channels each)
    int Cc  = tid & 63;                  // pooled column

    // ---- pooling: 4 channels x 4 rows = 16 independent coalesced loads ----
    {
        const float4* xf4 = (const float4*)x_feat;
        float acc = 0.f;
        #pragma unroll
        for (int cc = 0; cc < 4; ++cc) {
            int c = cg * 4 + cc;
            #pragma unroll
            for (int i = 0; i < 4; ++i) {
                // 64 lanes read 64 consecutive float4 (1KB contiguous)
                float4 v = __ldg(&xf4[((((b * C_IN + c) << 8) + (R * 4 + i)) << 6) + Cc]);
                acc += v.x + v.y + v.z + v.w;
            }
        }
        red[cg][Cc] = acc;
    }
    __syncthreads();

    // ---- final reduction over the 8 channel groups ----
    if (tid < 64) {
        float s = 0.f;
        #pragma unroll
        for (int g = 0; g < 8; ++g)
            s += red[g][tid];
        sums[tid] = s * (1.f / 16.f);
    }
    __syncthreads();

    // ---- nodes: 32 copies x 64 pix = 2048 stores, 4 per thread, coalesced ----
    {
        float* nodesb = out + (long)b * NODES_PER_B;
        #pragma unroll
        for (int k = 0; k < 4; ++k) {
            int sidx = tid + (k << 9);   // 0..2047
            int j    = sidx >> 6;        // copy 0..31
            int C    = sidx & 63;
            nodesb[j * NPIX + R * 64 + C] = sums[C];
        }
    }

    // ---- edges: 64 pix x 4 dirs = 256 tasks (threads 0..255) ----
    if (tid < 256) {
        int co  = tid >> 2;              // pooled col of destination t
        int sel = tid & 3;
        int t   = R * 64 + co;
        int f; bool valid;
        if      (sel == 0) { f = t - 64; valid = (R > 0);   }
        else if (sel == 1) { f = t + 64; valid = (R < 63);  }
        else if (sel == 2) { f = t - 1;  valid = (co > 0);  }
        else               { f = t + 1;  valid = (co < 63); }
        if (valid) {
            const float4* xv4 = (const float4*)x_var;
            float w = certainty(xv4, b, f) - certainty(xv4, b, t);
            if (w > EPSV)
                out[NODES_TOTAL + (long)b * ADJ_PER_B + (long)f * NPIX + t] = w;
        }
    }
}

extern "C" void kernel_launch(void* const* d_in, const int* in_sizes, int n_in,
                              void* d_out, int out_size)
{
    const float* x_feat = (const float*)d_in[0];
    const float* x_var  = (const float*)d_in[1];
    float* out = (float*)d_out;

    // Driver fill path (~6.4 TB/s, unbeatable by SASS stores): zero adj.
    cudaMemsetAsync(out + NODES_TOTAL, 0, (long)Bz * ADJ_PER_B * sizeof(float));

    // Single follow-up kernel: pooling + nodes + sparse edges.
    patch_all<<<256, 512>>>(x_feat, x_var, out);
}

// round 13
// speedup vs baseline: 1.1112x; 1.0012x over previous
#include <cuda_runtime.h>

#define Bz 4
#define C_IN 32
#define NPIX 4096                        // 64*64 pooled pixels
#define NODES_PER_B (NPIX * C_IN)        // 131072
#define NODES_TOTAL (Bz * NODES_PER_B)   // 524288
#define ADJ_PER_B   ((long)NPIX * NPIX)  // 16777216 floats
#define EPSV 1e-6f

// patch certainty for pooled pixel p of batch b (x_var is 1MB, L2-resident)
__device__ __forceinline__ float certainty(const float4* __restrict__ xv4, int b, int p)
{
    int R = p >> 6, C = p & 63;
    float s = 0.f;
    #pragma unroll
    for (int i = 0; i < 4; ++i) {
        float4 v = __ldg(&xv4[((b * 256 + (R * 4 + i)) << 6) + C]);
        s += v.x + v.y + v.z + v.w;
    }
    return 1.f - s * (1.f / 16.f);
}

// 256 blocks x 512 threads; block = one pooled row (b, R).
// 16 independent coalesced float4 loads per thread, 2 barriers,
// then tiled nodes stores + sparse edge patches (after memset, same stream).
__global__ __launch_bounds__(512) void patch_all(
    const float* __restrict__ x_feat,
    const float* __restrict__ x_var,
    float* __restrict__ out)
{
    __shared__ float red[8][64];         // [channel-group][Cc]
    __shared__ float sums[64];

    int blk = blockIdx.x;                // 0..255
    int b   = blk >> 6;                  // batch
    int R   = blk & 63;                  // pooled row

    int tid = threadIdx.x;               // 0..511
    int cg  = tid >> 6;                  // channel group (4 channels each)
    int Cc  = tid & 63;                  // pooled column

    // ---- pooling: 4 channels x 4 rows = 16 independent coalesced loads ----
    {
        const float4* xf4 = (const float4*)x_feat;
        float acc = 0.f;
        #pragma unroll
        for (int cc = 0; cc < 4; ++cc) {
            int c = cg * 4 + cc;
            #pragma unroll
            for (int i = 0; i < 4; ++i) {
                // 64 lanes read 64 consecutive float4 (1KB contiguous)
                float4 v = __ldg(&xf4[((((b * C_IN + c) << 8) + (R * 4 + i)) << 6) + Cc]);
                acc += v.x + v.y + v.z + v.w;
            }
        }
        red[cg][Cc] = acc;
    }
    __syncthreads();

    // ---- final reduction over the 8 channel groups ----
    if (tid < 64) {
        float s = 0.f;
        #pragma unroll
        for (int g = 0; g < 8; ++g)
            s += red[g][tid];
        sums[tid] = s * (1.f / 16.f);
    }
    __syncthreads();

    // ---- nodes: 32 copies x 64 pix = 2048 stores, 4 per thread, coalesced ----
    {
        float* nodesb = out + (long)b * NODES_PER_B;
        #pragma unroll
        for (int k = 0; k < 4; ++k) {
            int sidx = tid + (k << 9);   // 0..2047
            int j    = sidx >> 6;        // copy 0..31
            int C    = sidx & 63;
            nodesb[j * NPIX + R * 64 + C] = sums[C];
        }
    }

    // ---- edges: 64 pix x 4 dirs = 256 tasks (threads 0..255) ----
    if (tid < 256) {
        int co  = tid >> 2;              // pooled col of destination t
        int sel = tid & 3;
        int t   = R * 64 + co;
        int f; bool valid;
        if      (sel == 0) { f = t - 64; valid = (R > 0);   }
        else if (sel == 1) { f = t + 64; valid = (R < 63);  }
        else if (sel == 2) { f = t - 1;  valid = (co > 0);  }
        else               { f = t + 1;  valid = (co < 63); }
        if (valid) {
            const float4* xv4 = (const float4*)x_var;
            float w = certainty(xv4, b, f) - certainty(xv4, b, t);
            if (w > EPSV)
                out[NODES_TOTAL + (long)b * ADJ_PER_B + (long)f * NPIX + t] = w;
        }
    }
}

extern "C" void kernel_launch(void* const* d_in, const int* in_sizes, int n_in,
                              void* d_out, int out_size)
{
    const float* x_feat = (const float*)d_in[0];
    const float* x_var  = (const float*)d_in[1];
    float* out = (float*)d_out;

    // Driver fill path (~6.4 TB/s, unbeatable by SASS stores): zero adj.
    cudaMemsetAsync(out + NODES_TOTAL, 0, (long)Bz * ADJ_PER_B * sizeof(float));

    // Single follow-up kernel: pooling + nodes + sparse edges.
    patch_all<<<256, 512>>>(x_feat, x_var, out);
}

// round 14
// speedup vs baseline: 1.1317x; 1.0184x over previous
#include <cuda_runtime.h>

#define Bz 4
#define C_IN 32
#define NPIX 4096                        // 64*64 pooled pixels
#define NODES_PER_B (NPIX * C_IN)        // 131072
#define NODES_TOTAL (Bz * NODES_PER_B)   // 524288
#define ADJ_PER_B   ((long)NPIX * NPIX)  // 16777216 floats
#define EPSV 1e-6f

// patch certainty for pooled pixel p of batch b (x_var is 1MB, L2-resident)
__device__ __forceinline__ float certainty(const float4* __restrict__ xv4, int b, int p)
{
    int R = p >> 6, C = p & 63;
    float s = 0.f;
    #pragma unroll
    for (int i = 0; i < 4; ++i) {
        float4 v = __ldg(&xv4[((b * 256 + (R * 4 + i)) << 6) + C]);
        s += v.x + v.y + v.z + v.w;
    }
    return 1.f - s * (1.f / 16.f);
}

// 256 blocks x 512 threads; block = one pooled row (b, R).
// 16 independent coalesced float4 loads per thread, 2 barriers,
// then tiled nodes stores + sparse edge patches (after memset, same stream).
__global__ __launch_bounds__(512) void patch_all(
    const float* __restrict__ x_feat,
    const float* __restrict__ x_var,
    float* __restrict__ out)
{
    __shared__ float red[8][64];         // [channel-group][Cc]
    __shared__ float sums[64];

    int blk = blockIdx.x;                // 0..255
    int b   = blk >> 6;                  // batch
    int R   = blk & 63;                  // pooled row

    int tid = threadIdx.x;               // 0..511
    int cg  = tid >> 6;                  // channel group (4 channels each)
    int Cc  = tid & 63;                  // pooled column

    // ---- pooling: 4 channels x 4 rows = 16 independent coalesced loads ----
    {
        const float4* xf4 = (const float4*)x_feat;
        float acc = 0.f;
        #pragma unroll
        for (int cc = 0; cc < 4; ++cc) {
            int c = cg * 4 + cc;
            #pragma unroll
            for (int i = 0; i < 4; ++i) {
                // 64 lanes read 64 consecutive float4 (1KB contiguous)
                float4 v = __ldg(&xf4[((((b * C_IN + c) << 8) + (R * 4 + i)) << 6) + Cc]);
                acc += v.x + v.y + v.z + v.w;
            }
        }
        red[cg][Cc] = acc;
    }
    __syncthreads();

    // ---- final reduction over the 8 channel groups ----
    if (tid < 64) {
        float s = 0.f;
        #pragma unroll
        for (int g = 0; g < 8; ++g)
            s += red[g][tid];
        sums[tid] = s * (1.f / 16.f);
    }
    __syncthreads();

    // ---- nodes: 32 copies x 64 pix = 2048 stores, 4 per thread, coalesced ----
    {
        float* nodesb = out + (long)b * NODES_PER_B;
        #pragma unroll
        for (int k = 0; k < 4; ++k) {
            int sidx = tid + (k << 9);   // 0..2047
            int j    = sidx >> 6;        // copy 0..31
            int C    = sidx & 63;
            nodesb[j * NPIX + R * 64 + C] = sums[C];
        }
    }

    // ---- edges: 64 pix x 4 dirs = 256 tasks (threads 0..255) ----
    if (tid < 256) {
        int co  = tid >> 2;              // pooled col of destination t
        int sel = tid & 3;
        int t   = R * 64 + co;
        int f; bool valid;
        if      (sel == 0) { f = t - 64; valid = (R > 0);   }
        else if (sel == 1) { f = t + 64; valid = (R < 63);  }
        else if (sel == 2) { f = t - 1;  valid = (co > 0);  }
        else               { f = t + 1;  valid = (co < 63); }
        if (valid) {
            const float4* xv4 = (const float4*)x_var;
            float w = certainty(xv4, b, f) - certainty(xv4, b, t);
            if (w > EPSV)
                out[NODES_TOTAL + (long)b * ADJ_PER_B + (long)f * NPIX + t] = w;
        }
    }
}

extern "C" void kernel_launch(void* const* d_in, const int* in_sizes, int n_in,
                              void* d_out, int out_size)
{
    const float* x_feat = (const float*)d_in[0];
    const float* x_var  = (const float*)d_in[1];
    float* out = (float*)d_out;

    // Driver fill path (~6.4 TB/s, unbeatable by SASS stores): zero adj.
    cudaMemsetAsync(out + NODES_TOTAL, 0, (long)Bz * ADJ_PER_B * sizeof(float));

    // Single follow-up kernel: pooling + nodes + sparse edges.
    patch_all<<<256, 512>>>(x_feat, x_var, out);
}